// round 1
// baseline (speedup 1.0000x reference)
#include <cuda_runtime.h>
#include <math.h>

#define BB 32
#define SS 2048
#define HH 1024

// Scratch (device globals: allocation-free per harness rules)
__device__ float g_qw[BB * HH];       // qW + Wa_b + Ua_b, per (b,h)
__device__ float g_scores[BB * SS];   // raw scores, then overwritten with softmax weights

// ---------------------------------------------------------------------------
// Kernel 1: qw[b][h] = sum_i q[b][i] * Wa[i][h] + Wa_b[h] + Ua_b[h]
// grid (H/256, B/4), 256 threads. Each block handles 4 batches to reuse Wa.
// ---------------------------------------------------------------------------
__global__ void qw_kernel(const float* __restrict__ q,
                          const float* __restrict__ Wa,
                          const float* __restrict__ Wab,
                          const float* __restrict__ Uab) {
    const int h  = blockIdx.x * 256 + threadIdx.x;
    const int b0 = blockIdx.y * 4;
    __shared__ float qs[4][HH];

    for (int idx = threadIdx.x; idx < 4 * HH; idx += 256) {
        qs[idx / HH][idx % HH] = q[(b0 + idx / HH) * HH + (idx % HH)];
    }
    __syncthreads();

    float acc0 = 0.f, acc1 = 0.f, acc2 = 0.f, acc3 = 0.f;
#pragma unroll 4
    for (int i = 0; i < HH; i++) {
        const float w = Wa[i * HH + h];
        acc0 += qs[0][i] * w;
        acc1 += qs[1][i] * w;
        acc2 += qs[2][i] * w;
        acc3 += qs[3][i] * w;
    }
    const float bias = Wab[h] + Uab[h];
    g_qw[(b0 + 0) * HH + h] = acc0 + bias;
    g_qw[(b0 + 1) * HH + h] = acc1 + bias;
    g_qw[(b0 + 2) * HH + h] = acc2 + bias;
    g_qw[(b0 + 3) * HH + h] = acc3 + bias;
}

// ---------------------------------------------------------------------------
// Kernel 2 (dominant): fused  scores[b][s] = sum_h tanh(qw[b][h] + (k@Ua)[b][s][h]) * va[h]
// Tiled GEMM: BM=64 (s rows), BN=64 (h cols), BK=16, 256 threads, 4x4 microtile.
// grid (S/64, B).
// ---------------------------------------------------------------------------
__global__ void scores_kernel(const float* __restrict__ key,   // (S, B, H)
                              const float* __restrict__ Ua,    // (H, H)
                              const float* __restrict__ va) {  // (H)
    const int b  = blockIdx.y;
    const int s0 = blockIdx.x * 64;

    __shared__ float As[16][64];       // [k][m]  (key tile, transposed)
    __shared__ float Bs[16][64];       // [k][n]  (Ua tile)
    __shared__ float qs[64];           // qw tile for this h-block
    __shared__ float vs[64];           // va tile
    __shared__ float red[64][17];      // cross-thread reduction (padded)

    const int tid = threadIdx.x;       // 0..255
    const int tx  = tid & 15;          // n-dim microtile index
    const int ty  = tid >> 4;          // m-dim microtile index

    // A-load indices: 64 rows x 16 k, one float4 per thread along k
    const int ar  = tid >> 2;          // 0..63 row
    const int ac4 = (tid & 3) * 4;     // 0,4,8,12
    // B-load indices: 16 k-rows x 64 cols, one float4 per thread along n
    const int bk  = tid >> 4;          // 0..15
    const int bc4 = (tid & 15) * 4;    // 0..60

    const float* keyRow = key + ((size_t)(s0 + ar) * BB + b) * HH + ac4;

    float rowacc[4] = {0.f, 0.f, 0.f, 0.f};

    for (int h0 = 0; h0 < HH; h0 += 64) {
        if (tid < 64) {
            qs[tid] = g_qw[b * HH + h0 + tid];
            vs[tid] = va[h0 + tid];
        }

        float acc[4][4];
#pragma unroll
        for (int i = 0; i < 4; i++)
#pragma unroll
            for (int j = 0; j < 4; j++) acc[i][j] = 0.f;

        for (int k0 = 0; k0 < HH; k0 += 16) {
            // load key tile (coalesced along k)
            {
                const float4 v = *(const float4*)(keyRow + k0);
                As[ac4 + 0][ar] = v.x;
                As[ac4 + 1][ar] = v.y;
                As[ac4 + 2][ar] = v.z;
                As[ac4 + 3][ar] = v.w;
            }
            // load Ua tile (coalesced along n)
            {
                const float4 v = *(const float4*)&Ua[(size_t)(k0 + bk) * HH + h0 + bc4];
                *(float4*)&Bs[bk][bc4] = v;
            }
            __syncthreads();

#pragma unroll
            for (int k = 0; k < 16; k++) {
                const float4 av = *(const float4*)&As[k][ty * 4];
                const float4 bv = *(const float4*)&Bs[k][tx * 4];
                acc[0][0] += av.x * bv.x; acc[0][1] += av.x * bv.y;
                acc[0][2] += av.x * bv.z; acc[0][3] += av.x * bv.w;
                acc[1][0] += av.y * bv.x; acc[1][1] += av.y * bv.y;
                acc[1][2] += av.y * bv.z; acc[1][3] += av.y * bv.w;
                acc[2][0] += av.z * bv.x; acc[2][1] += av.z * bv.y;
                acc[2][2] += av.z * bv.z; acc[2][3] += av.z * bv.w;
                acc[3][0] += av.w * bv.x; acc[3][1] += av.w * bv.y;
                acc[3][2] += av.w * bv.z; acc[3][3] += av.w * bv.w;
            }
            __syncthreads();
        }

        // Epilogue for this h-block: tanh(acc + qw) * va, reduce over n
#pragma unroll
        for (int i = 0; i < 4; i++) {
            float p = 0.f;
#pragma unroll
            for (int j = 0; j < 4; j++) {
                const int hh = tx * 4 + j;
                p += tanhf(acc[i][j] + qs[hh]) * vs[hh];
            }
            rowacc[i] += p;
        }
        __syncthreads();  // protect qs/vs before next h-block rewrites them
    }

    // Reduce partial row sums across the 16 tx-lanes
#pragma unroll
    for (int i = 0; i < 4; i++) red[ty * 4 + i][tx] = rowacc[i];
    __syncthreads();
    if (tid < 64) {
        float s = 0.f;
#pragma unroll
        for (int j = 0; j < 16; j++) s += red[tid][j];
        g_scores[b * SS + s0 + tid] = s;
    }
}

// ---------------------------------------------------------------------------
// Kernel 3: softmax over S per batch. Writes weights to out[B*H + b*S + s]
// and back into g_scores for the context kernel. (va_b dropped: softmax-invariant)
// grid (B), 256 threads, 8 values/thread.
// ---------------------------------------------------------------------------
__global__ void softmax_kernel(float* __restrict__ out) {
    const int b   = blockIdx.x;
    const int tid = threadIdx.x;
    __shared__ float red[256];

    float local[8];
    float mx = -1e30f;
#pragma unroll
    for (int j = 0; j < 8; j++) {
        local[j] = g_scores[b * SS + tid + j * 256];
        mx = fmaxf(mx, local[j]);
    }
    red[tid] = mx;
    __syncthreads();
    for (int off = 128; off > 0; off >>= 1) {
        if (tid < off) red[tid] = fmaxf(red[tid], red[tid + off]);
        __syncthreads();
    }
    const float m = red[0];
    __syncthreads();

    float sum = 0.f;
#pragma unroll
    for (int j = 0; j < 8; j++) {
        local[j] = expf(local[j] - m);
        sum += local[j];
    }
    red[tid] = sum;
    __syncthreads();
    for (int off = 128; off > 0; off >>= 1) {
        if (tid < off) red[tid] += red[tid + off];
        __syncthreads();
    }
    const float inv = 1.0f / red[0];

#pragma unroll
    for (int j = 0; j < 8; j++) {
        const float w = local[j] * inv;
        const int s = tid + j * 256;
        out[BB * HH + b * SS + s] = w;
        g_scores[b * SS + s] = w;   // reuse as weights for context kernel
    }
}

// ---------------------------------------------------------------------------
// Kernel 4: context[b][h] = sum_s w[b][s] * key[s][b][h]. Memory-bound (256 MB).
// grid (H/256, B), 256 threads.
// ---------------------------------------------------------------------------
__global__ void context_kernel(const float* __restrict__ key,
                               float* __restrict__ out) {
    const int b = blockIdx.y;
    const int h = blockIdx.x * 256 + threadIdx.x;
    __shared__ float ws[256];

    float acc = 0.f;
    for (int sb = 0; sb < SS; sb += 256) {
        __syncthreads();
        ws[threadIdx.x] = g_scores[b * SS + sb + threadIdx.x];
        __syncthreads();
#pragma unroll 4
        for (int s = 0; s < 256; s++) {
            acc += ws[s] * key[((size_t)(sb + s) * BB + b) * HH + h];
        }
    }
    out[b * HH + h] = acc;
}

// ---------------------------------------------------------------------------
extern "C" void kernel_launch(void* const* d_in, const int* in_sizes, int n_in,
                              void* d_out, int out_size) {
    const float* query = (const float*)d_in[0];  // (B,1,H)
    const float* key   = (const float*)d_in[1];  // (S,B,H)
    const float* Wa_w  = (const float*)d_in[2];  // (H,H)
    const float* Wa_b  = (const float*)d_in[3];  // (H)
    const float* Ua_w  = (const float*)d_in[4];  // (H,H)
    const float* Ua_b  = (const float*)d_in[5];  // (H)
    const float* va_w  = (const float*)d_in[6];  // (H)
    // d_in[7] = va_b: uniform additive shift before softmax -> invariant, unused.
    float* out = (float*)d_out;                  // [context (B*H) | weights (B*S)]

    qw_kernel<<<dim3(HH / 256, BB / 4), 256>>>(query, Wa_w, Wa_b, Ua_b);
    scores_kernel<<<dim3(SS / 64, BB), 256>>>(key, Ua_w, va_w);
    softmax_kernel<<<BB, 256>>>(out);
    context_kernel<<<dim3(HH / 256, BB), 256>>>(key, out);
}

// round 3
// speedup vs baseline: 4.7461x; 4.7461x over previous
#include <cuda_runtime.h>
#include <cuda_fp16.h>
#include <math.h>
#include <stdint.h>

#define BB 32
#define SS 2048
#define HH 1024

// ---------------- device scratch ----------------
__device__ float  g_qw[BB * HH];
__device__ float  g_scores[BB * SS];
__device__ __half g_k16[(size_t)SS * BB * HH];   // key fp16, same (S,B,H) layout
__device__ __half g_uT16[(size_t)HH * HH];       // Ua^T fp16, [n][k]
__device__ float  g_ctx_part[16 * BB * HH];

// ---------------- helpers (base-ISA only) ----------------
__device__ __forceinline__ uint32_t smem_u32(const void* p) {
    uint32_t a;
    asm("{ .reg .u64 t; cvta.to.shared.u64 t, %1; cvt.u32.u64 %0, t; }" : "=r"(a) : "l"(p));
    return a;
}
__device__ __forceinline__ void cp16(uint32_t dst, const void* src) {
    asm volatile("cp.async.cg.shared.global [%0], [%1], 16;" :: "r"(dst), "l"(src));
}
__device__ __forceinline__ void cp_commit() { asm volatile("cp.async.commit_group;"); }
__device__ __forceinline__ void ldsm4(uint32_t* r, uint32_t a) {
    asm volatile("ldmatrix.sync.aligned.m8n8.x4.shared.b16 {%0,%1,%2,%3}, [%4];"
                 : "=r"(r[0]), "=r"(r[1]), "=r"(r[2]), "=r"(r[3]) : "r"(a));
}
__device__ __forceinline__ void mma16816(float* c, const uint32_t* a, const uint32_t* b) {
    asm volatile(
        "mma.sync.aligned.m16n8k16.row.col.f32.f16.f16.f32 "
        "{%0,%1,%2,%3}, {%4,%5,%6,%7}, {%8,%9}, {%0,%1,%2,%3};"
        : "+f"(c[0]), "+f"(c[1]), "+f"(c[2]), "+f"(c[3])
        : "r"(a[0]), "r"(a[1]), "r"(a[2]), "r"(a[3]), "r"(b[0]), "r"(b[1]));
}
// accurate tanh via ex2/rcp MUFU: (e^{2x}-1)/(e^{2x}+1), err ~1e-6
__device__ __forceinline__ float fast_tanh(float x) {
    x = fminf(15.f, fmaxf(-15.f, x));
    float t, r;
    asm("ex2.approx.f32 %0, %1;" : "=f"(t) : "f"(x * 2.885390082f));  // 2*log2(e)
    asm("rcp.approx.f32 %0, %1;" : "=f"(r) : "f"(t + 1.0f));
    return (t - 1.0f) * r;
}

// ---------------------------------------------------------------------------
// key fp32 -> fp16 (same (S,B,H) layout)
// ---------------------------------------------------------------------------
__global__ void convert_key_kernel(const float4* __restrict__ k4) {
    const size_t i = (size_t)blockIdx.x * 256 + threadIdx.x;  // 16.7M float4
    const float4 v = k4[i];
    __half2* dst = (__half2*)g_k16;
    dst[i * 2 + 0] = __floats2half2_rn(v.x, v.y);
    dst[i * 2 + 1] = __floats2half2_rn(v.z, v.w);
}

// ---------------------------------------------------------------------------
// Ua (H,H) -> Ua^T fp16 [n][k]
// ---------------------------------------------------------------------------
__global__ void convert_ua_kernel(const float* __restrict__ Ua) {
    __shared__ float tile[32][33];
    const int k0 = blockIdx.x * 32, n0 = blockIdx.y * 32;
    const int tx = threadIdx.x, ty = threadIdx.y;  // (32, 8)
#pragma unroll
    for (int r = 0; r < 4; r++)
        tile[ty + r * 8][tx] = Ua[(size_t)(k0 + ty + r * 8) * HH + n0 + tx];
    __syncthreads();
#pragma unroll
    for (int r = 0; r < 4; r++)
        g_uT16[(size_t)(n0 + ty + r * 8) * HH + k0 + tx] = __float2half(tile[tx][ty + r * 8]);
}

// ---------------------------------------------------------------------------
// qw[b][h] = q[b] @ Wa + Wa_b + Ua_b   (fp32, trivial)
// ---------------------------------------------------------------------------
__global__ void qw_kernel(const float* __restrict__ q, const float* __restrict__ Wa,
                          const float* __restrict__ Wab, const float* __restrict__ Uab) {
    const int h  = blockIdx.x * 256 + threadIdx.x;
    const int b0 = blockIdx.y * 4;
    __shared__ float qs[4][HH];
    for (int idx = threadIdx.x; idx < 4 * HH; idx += 256)
        qs[idx / HH][idx % HH] = q[(b0 + idx / HH) * HH + (idx % HH)];
    __syncthreads();
    float a0 = 0.f, a1 = 0.f, a2 = 0.f, a3 = 0.f;
#pragma unroll 4
    for (int i = 0; i < HH; i++) {
        const float w = Wa[(size_t)i * HH + h];
        a0 += qs[0][i] * w; a1 += qs[1][i] * w; a2 += qs[2][i] * w; a3 += qs[3][i] * w;
    }
    const float bias = Wab[h] + Uab[h];
    g_qw[(b0 + 0) * HH + h] = a0 + bias;
    g_qw[(b0 + 1) * HH + h] = a1 + bias;
    g_qw[(b0 + 2) * HH + h] = a2 + bias;
    g_qw[(b0 + 3) * HH + h] = a3 + bias;
}

// ---------------------------------------------------------------------------
// scores via mma.sync fp16: per CTA (b, 128 s-rows):
//   scores[s] = sum_h tanh((K @ UaT^T)[s][h] + qw[h]) * va[h]
// BM=128, BN=128, BK=64; 8 warps, warp tile 32x64; cp.async double buffer.
// ---------------------------------------------------------------------------
#define BM 128
#define BN 128
#define BK 64
#define NKT (HH / BK)   // 16
#define NNC (HH / BN)   // 8

#define SM_QW  0u        // 4096 B
#define SM_VA  4096u     // 4096 B
#define SM_RED 8192u     // 1024 B
#define SM_A0  16384u    // 16 KB
#define SM_A1  32768u
#define SM_B0  49152u    // 16 KB
#define SM_B1  65536u
#define SM_TOT 81920u

__global__ void __launch_bounds__(256, 2)
scores_kernel(const float* __restrict__ va) {
    extern __shared__ char sm[];
    const int tid = threadIdx.x, lane = tid & 31, wid = tid >> 5;
    const int wm = wid & 3, wn = wid >> 2;     // warp grid 4(m) x 2(n)
    const int b = blockIdx.y, s0 = blockIdx.x * BM;
    const uint32_t sb = smem_u32(sm);
    float* s_qw  = (float*)(sm + SM_QW);
    float* s_va  = (float*)(sm + SM_VA);
    float* s_red = (float*)(sm + SM_RED);

#pragma unroll
    for (int i = 0; i < 4; i++) {
        s_qw[tid + i * 256] = g_qw[b * HH + tid + i * 256];
        s_va[tid + i * 256] = va[tid + i * 256];
    }

    // cp.async per-thread assignments: tiles are 128 rows x 8 segs(16B), swizzled
    uint32_t a_dst[4], b_dst[4];
    const __half* a_src[4];
    uint32_t b_off[4];
#pragma unroll
    for (int i = 0; i < 4; i++) {
        const int c = tid + i * 256, row = c >> 3, seg = c & 7;
        a_dst[i] = (uint32_t)(row * 128 + ((seg ^ (row & 7)) << 4));
        a_src[i] = g_k16 + ((size_t)(s0 + row) * BB + b) * HH + seg * 8;
        b_dst[i] = a_dst[i];
        b_off[i] = (uint32_t)(row * HH + seg * 8);
    }

    // ldmatrix per-lane row/seg components
    const int arow = wm * 32 + (lane & 15);                    // + 16 for 2nd m-frag
    const int aseg = lane >> 4;                                // 0/1 (k +0/+8)
    const int brow = wn * 64 + (lane & 7) + ((lane & 16) >> 1);// + t*16 per n16 group
    const int bseg = (lane >> 3) & 1;
    const int swz  = lane & 7;

    float rowacc[4] = {0.f, 0.f, 0.f, 0.f};

    for (int nc = 0; nc < NNC; nc++) {
        const int n0 = nc * BN;
        const __half* uT = g_uT16 + (size_t)n0 * HH;

        float acc[2][8][4];
#pragma unroll
        for (int mf = 0; mf < 2; mf++)
#pragma unroll
            for (int nf = 0; nf < 8; nf++)
#pragma unroll
                for (int j = 0; j < 4; j++) acc[mf][nf][j] = 0.f;

        // prologue: k-tile 0 -> buffer 0
#pragma unroll
        for (int i = 0; i < 4; i++) {
            cp16(sb + SM_A0 + a_dst[i], a_src[i]);
            cp16(sb + SM_B0 + b_dst[i], uT + b_off[i]);
        }
        cp_commit();

        for (int kt = 0; kt < NKT; kt++) {
            const uint32_t Ab = sb + ((kt & 1) ? SM_A1 : SM_A0);
            const uint32_t Bb = sb + ((kt & 1) ? SM_B1 : SM_B0);
            if (kt + 1 < NKT) {
                const uint32_t An = sb + ((kt & 1) ? SM_A0 : SM_A1);
                const uint32_t Bn = sb + ((kt & 1) ? SM_B0 : SM_B1);
                const int k0 = (kt + 1) * BK;
#pragma unroll
                for (int i = 0; i < 4; i++) {
                    cp16(An + a_dst[i], a_src[i] + k0);
                    cp16(Bn + b_dst[i], uT + b_off[i] + k0);
                }
                cp_commit();
                asm volatile("cp.async.wait_group 1;");
            } else {
                asm volatile("cp.async.wait_group 0;");
            }
            __syncthreads();

#pragma unroll
            for (int q = 0; q < 4; q++) {
                uint32_t a0[4], a1[4];
                const uint32_t aa = Ab + (uint32_t)(arow * 128 + (((q * 2 + aseg) ^ swz) << 4));
                ldsm4(a0, aa);
                ldsm4(a1, aa + 16 * 128);
                uint32_t breg[4][4];
                const uint32_t ba = Bb + (uint32_t)(brow * 128 + (((q * 2 + bseg) ^ swz) << 4));
#pragma unroll
                for (int t = 0; t < 4; t++) ldsm4(breg[t], ba + (uint32_t)(t * 16 * 128));
#pragma unroll
                for (int mf = 0; mf < 2; mf++) {
                    uint32_t* A = mf ? a1 : a0;
#pragma unroll
                    for (int nf = 0; nf < 8; nf++)
                        mma16816(acc[mf][nf], A, breg[nf >> 1] + (nf & 1) * 2);
                }
            }
            __syncthreads();
        }

        // epilogue: tanh(acc + qw)*va, accumulate per-row partials
#pragma unroll
        for (int mf = 0; mf < 2; mf++)
#pragma unroll
            for (int nf = 0; nf < 8; nf++) {
                const int h0 = n0 + wn * 64 + nf * 8 + (lane & 3) * 2;
                const float q0 = s_qw[h0], q1 = s_qw[h0 + 1];
                const float v0 = s_va[h0], v1 = s_va[h0 + 1];
                float* c = acc[mf][nf];
                rowacc[mf * 2 + 0] += fast_tanh(c[0] + q0) * v0 + fast_tanh(c[1] + q1) * v1;
                rowacc[mf * 2 + 1] += fast_tanh(c[2] + q0) * v0 + fast_tanh(c[3] + q1) * v1;
            }
    }

    // reduce over the 4 col-lanes of each quad
#pragma unroll
    for (int d = 1; d < 4; d <<= 1)
#pragma unroll
        for (int i = 0; i < 4; i++)
            rowacc[i] += __shfl_xor_sync(0xffffffffu, rowacc[i], d);

    if ((lane & 3) == 0) {
        const int r0 = wm * 32 + (lane >> 2);
        s_red[(r0 +  0) * 2 + wn] = rowacc[0];
        s_red[(r0 +  8) * 2 + wn] = rowacc[1];
        s_red[(r0 + 16) * 2 + wn] = rowacc[2];
        s_red[(r0 + 24) * 2 + wn] = rowacc[3];
    }
    __syncthreads();
    if (tid < 128)
        g_scores[b * SS + s0 + tid] = s_red[tid * 2] + s_red[tid * 2 + 1];
}

// ---------------------------------------------------------------------------
// softmax over S per batch (va_b softmax-invariant, dropped)
// ---------------------------------------------------------------------------
__global__ void softmax_kernel(float* __restrict__ out) {
    const int b = blockIdx.x, tid = threadIdx.x;
    __shared__ float red[256];
    float local[8];
    float mx = -1e30f;
#pragma unroll
    for (int j = 0; j < 8; j++) {
        local[j] = g_scores[b * SS + tid + j * 256];
        mx = fmaxf(mx, local[j]);
    }
    red[tid] = mx; __syncthreads();
    for (int off = 128; off > 0; off >>= 1) {
        if (tid < off) red[tid] = fmaxf(red[tid], red[tid + off]);
        __syncthreads();
    }
    const float m = red[0]; __syncthreads();
    float sum = 0.f;
#pragma unroll
    for (int j = 0; j < 8; j++) { local[j] = expf(local[j] - m); sum += local[j]; }
    red[tid] = sum; __syncthreads();
    for (int off = 128; off > 0; off >>= 1) {
        if (tid < off) red[tid] += red[tid + off];
        __syncthreads();
    }
    const float inv = 1.0f / red[0];
#pragma unroll
    for (int j = 0; j < 8; j++) {
        const float w = local[j] * inv;
        const int s = tid + j * 256;
        out[BB * HH + b * SS + s] = w;
        g_scores[b * SS + s] = w;
    }
}

// ---------------------------------------------------------------------------
// context: partials over 16 s-chunks, then reduce (deterministic)
// ---------------------------------------------------------------------------
__global__ void context_part_kernel(const float* __restrict__ key) {
    const int b = blockIdx.x, sp = blockIdx.y, tid = threadIdx.x;
    const int s0 = sp * 128;
    __shared__ float ws[128];
    if (tid < 128) ws[tid] = g_scores[b * SS + s0 + tid];
    __syncthreads();
    float4 acc = make_float4(0.f, 0.f, 0.f, 0.f);
    const float4* kp = (const float4*)key + ((size_t)s0 * BB + b) * 256 + tid;
#pragma unroll 4
    for (int s = 0; s < 128; s++) {
        const float  w = ws[s];
        const float4 v = kp[(size_t)s * 8192];
        acc.x += w * v.x; acc.y += w * v.y; acc.z += w * v.z; acc.w += w * v.w;
    }
    ((float4*)g_ctx_part)[((size_t)sp * BB + b) * 256 + tid] = acc;
}

__global__ void ctx_reduce_kernel(float* __restrict__ out) {
    const int t = blockIdx.x * 256 + threadIdx.x;  // 8192 float4 outputs
    float4 acc = make_float4(0.f, 0.f, 0.f, 0.f);
#pragma unroll
    for (int sp = 0; sp < 16; sp++) {
        const float4 v = ((const float4*)g_ctx_part)[(size_t)sp * 8192 + t];
        acc.x += v.x; acc.y += v.y; acc.z += v.z; acc.w += v.w;
    }
    ((float4*)out)[t] = acc;
}

// ---------------------------------------------------------------------------
extern "C" void kernel_launch(void* const* d_in, const int* in_sizes, int n_in,
                              void* d_out, int out_size) {
    (void)in_sizes; (void)n_in; (void)out_size;
    const float* query = (const float*)d_in[0];
    const float* key   = (const float*)d_in[1];
    const float* Wa_w  = (const float*)d_in[2];
    const float* Wa_b  = (const float*)d_in[3];
    const float* Ua_w  = (const float*)d_in[4];
    const float* Ua_b  = (const float*)d_in[5];
    const float* va_w  = (const float*)d_in[6];
    float* out = (float*)d_out;  // [context (B*H) | weights (B*S)]

    cudaFuncSetAttribute(scores_kernel, cudaFuncAttributeMaxDynamicSharedMemorySize, SM_TOT);

    convert_key_kernel<<<65536, 256>>>((const float4*)key);
    convert_ua_kernel<<<dim3(HH / 32, HH / 32), dim3(32, 8)>>>(Ua_w);
    qw_kernel<<<dim3(HH / 256, BB / 4), 256>>>(query, Wa_w, Wa_b, Ua_b);
    scores_kernel<<<dim3(SS / BM, BB), 256, SM_TOT>>>(va_w);
    softmax_kernel<<<BB, 256>>>(out);
    context_part_kernel<<<dim3(BB, 16), 256>>>(key);
    ctx_reduce_kernel<<<32, 256>>>(out);
}

// round 5
// speedup vs baseline: 7.2240x; 1.5221x over previous
#include <cuda_runtime.h>
#include <cuda_fp16.h>
#include <math.h>
#include <stdint.h>

#define BB 32
#define SS 2048
#define HH 1024

// ---------------- device scratch ----------------
__device__ float  g_qw[BB * HH];
__device__ float  g_scores[BB * SS];
__device__ __half g_k16[(size_t)SS * BB * HH];   // key fp16, same (S,B,H) layout
__device__ __half g_uT16[(size_t)HH * HH];       // Ua^T fp16, [n][k]
__device__ float  g_ctx_part[16 * BB * HH];

// ---------------- helpers (base-ISA only) ----------------
__device__ __forceinline__ uint32_t smem_u32(const void* p) {
    uint32_t a;
    asm("{ .reg .u64 t; cvta.to.shared.u64 t, %1; cvt.u32.u64 %0, t; }" : "=r"(a) : "l"(p));
    return a;
}
__device__ __forceinline__ void cp16(uint32_t dst, const void* src) {
    asm volatile("cp.async.cg.shared.global [%0], [%1], 16;" :: "r"(dst), "l"(src));
}
__device__ __forceinline__ void cp_commit() { asm volatile("cp.async.commit_group;"); }
__device__ __forceinline__ void ldsm4(uint32_t* r, uint32_t a) {
    asm volatile("ldmatrix.sync.aligned.m8n8.x4.shared.b16 {%0,%1,%2,%3}, [%4];"
                 : "=r"(r[0]), "=r"(r[1]), "=r"(r[2]), "=r"(r[3]) : "r"(a));
}
__device__ __forceinline__ void mma16816(float* c, const uint32_t* a, const uint32_t* b) {
    asm volatile(
        "mma.sync.aligned.m16n8k16.row.col.f32.f16.f16.f32 "
        "{%0,%1,%2,%3}, {%4,%5,%6,%7}, {%8,%9}, {%0,%1,%2,%3};"
        : "+f"(c[0]), "+f"(c[1]), "+f"(c[2]), "+f"(c[3])
        : "r"(a[0]), "r"(a[1]), "r"(a[2]), "r"(a[3]), "r"(b[0]), "r"(b[1]));
}
__device__ __forceinline__ float fast_tanh(float x) {
    float y; asm("tanh.approx.f32 %0, %1;" : "=f"(y) : "f"(x)); return y;
}

// ---------------------------------------------------------------------------
// key fp32 -> fp16 (same (S,B,H) layout)
// ---------------------------------------------------------------------------
__global__ void convert_key_kernel(const float4* __restrict__ k4) {
    const size_t i = (size_t)blockIdx.x * 256 + threadIdx.x;  // 16.7M float4
    const float4 v = k4[i];
    __half2* dst = (__half2*)g_k16;
    dst[i * 2 + 0] = __floats2half2_rn(v.x, v.y);
    dst[i * 2 + 1] = __floats2half2_rn(v.z, v.w);
}

// ---------------------------------------------------------------------------
// Ua (H,H) -> Ua^T fp16 [n][k]
// ---------------------------------------------------------------------------
__global__ void convert_ua_kernel(const float* __restrict__ Ua) {
    __shared__ float tile[32][33];
    const int k0 = blockIdx.x * 32, n0 = blockIdx.y * 32;
    const int tx = threadIdx.x, ty = threadIdx.y;  // (32, 8)
#pragma unroll
    for (int r = 0; r < 4; r++)
        tile[ty + r * 8][tx] = Ua[(size_t)(k0 + ty + r * 8) * HH + n0 + tx];
    __syncthreads();
#pragma unroll
    for (int r = 0; r < 4; r++)
        g_uT16[(size_t)(n0 + ty + r * 8) * HH + k0 + tx] = __float2half(tile[tx][ty + r * 8]);
}

// ---------------------------------------------------------------------------
// qw[b][h] = q[b] @ Wa + Wa_b + Ua_b   (fp32, trivial)
// ---------------------------------------------------------------------------
__global__ void qw_kernel(const float* __restrict__ q, const float* __restrict__ Wa,
                          const float* __restrict__ Wab, const float* __restrict__ Uab) {
    const int h  = blockIdx.x * 256 + threadIdx.x;
    const int b0 = blockIdx.y * 4;
    __shared__ float qs[4][HH];
    for (int idx = threadIdx.x; idx < 4 * HH; idx += 256)
        qs[idx / HH][idx % HH] = q[(b0 + idx / HH) * HH + (idx % HH)];
    __syncthreads();
    float a0 = 0.f, a1 = 0.f, a2 = 0.f, a3 = 0.f;
#pragma unroll 4
    for (int i = 0; i < HH; i++) {
        const float w = Wa[(size_t)i * HH + h];
        a0 += qs[0][i] * w; a1 += qs[1][i] * w; a2 += qs[2][i] * w; a3 += qs[3][i] * w;
    }
    const float bias = Wab[h] + Uab[h];
    g_qw[(b0 + 0) * HH + h] = a0 + bias;
    g_qw[(b0 + 1) * HH + h] = a1 + bias;
    g_qw[(b0 + 2) * HH + h] = a2 + bias;
    g_qw[(b0 + 3) * HH + h] = a3 + bias;
}

// ---------------------------------------------------------------------------
// scores via mma.sync fp16: flattened 128-tile loop (8 n-chunks x 16 k-tiles),
// 3-stage cp.async pipeline, ONE __syncthreads per tile.
// BM=128, BN=128, BK=64; 8 warps (4m x 2n), warp tile 32x64.
// ---------------------------------------------------------------------------
#define BM 128
#define BN 128
#define BK 64
#define NKT   (HH / BK)           // 16
#define NNC   (HH / BN)           // 8
#define NTILE (NKT * NNC)         // 128

#define SM_QW   0u                 // 4 KB
#define SM_VA   4096u              // 4 KB
#define SM_RED  8192u              // 1 KB
#define SM_TILE 12288u             // 3 stages x (16KB A + 16KB B)
#define STAGE_B 32768u
#define SM_TOT  (SM_TILE + 3u * STAGE_B)   // 110592 B

__global__ void __launch_bounds__(256, 2)
scores_kernel(const float* __restrict__ va) {
    extern __shared__ char sm[];
    const int tid = threadIdx.x, lane = tid & 31, wid = tid >> 5;
    const int wm = wid & 3, wn = wid >> 2;     // warp grid 4(m) x 2(n)
    const int b = blockIdx.y, s0 = blockIdx.x * BM;
    const uint32_t sb = smem_u32(sm);
    float* s_qw  = (float*)(sm + SM_QW);
    float* s_va  = (float*)(sm + SM_VA);
    float* s_red = (float*)(sm + SM_RED);

#pragma unroll
    for (int i = 0; i < 4; i++) {
        s_qw[tid + i * 256] = g_qw[b * HH + tid + i * 256];
        s_va[tid + i * 256] = va[tid + i * 256];
    }

    // cp.async per-thread assignments: 128 rows x 8 segs(16B), XOR swizzle.
    // A and B tiles use the IDENTICAL swizzle pattern (a_dst serves both).
    uint32_t a_dst[4];
    const __half* a_src[4];
    uint32_t b_off[4];
#pragma unroll
    for (int i = 0; i < 4; i++) {
        const int c = tid + i * 256, row = c >> 3, seg = c & 7;
        a_dst[i] = (uint32_t)(row * 128 + ((seg ^ (row & 7)) << 4));
        a_src[i] = g_k16 + ((size_t)(s0 + row) * BB + b) * HH + seg * 8;
        b_off[i] = (uint32_t)(row * HH + seg * 8);
    }

    // ldmatrix per-lane components
    const int arow = wm * 32 + (lane & 15);
    const int aseg = lane >> 4;
    const int brow = wn * 64 + (lane & 7) + ((lane & 16) >> 1);
    const int bseg = (lane >> 3) & 1;
    const int swz  = lane & 7;

    float rowacc[4] = {0.f, 0.f, 0.f, 0.f};
    float acc[2][8][4];
#pragma unroll
    for (int mf = 0; mf < 2; mf++)
#pragma unroll
        for (int nf = 0; nf < 8; nf++)
#pragma unroll
            for (int j = 0; j < 4; j++) acc[mf][nf][j] = 0.f;

    // tile issuer: tile t -> stage t%3
    auto issue = [&](int t) {
        const int nc = t >> 4, kt = t & 15, k0 = kt * BK;
        const uint32_t st = sb + SM_TILE + (uint32_t)(t % 3) * STAGE_B;
        const __half* uTp = g_uT16 + (size_t)(nc * BN) * HH + k0;
#pragma unroll
        for (int i = 0; i < 4; i++) cp16(st + a_dst[i], a_src[i] + k0);
#pragma unroll
        for (int i = 0; i < 4; i++) cp16(st + 16384u + a_dst[i], uTp + b_off[i]);
        cp_commit();
    };

    issue(0);
    issue(1);

    for (int t = 0; t < NTILE; t++) {
        if (t + 1 < NTILE) asm volatile("cp.async.wait_group 1;");
        else               asm volatile("cp.async.wait_group 0;");
        __syncthreads();
        if (t + 2 < NTILE) issue(t + 2);

        const uint32_t Ab = sb + SM_TILE + (uint32_t)(t % 3) * STAGE_B;
        const uint32_t Bb = Ab + 16384u;

#pragma unroll
        for (int q = 0; q < 4; q++) {
            uint32_t a0[4], a1[4];
            const uint32_t aa = Ab + (uint32_t)(arow * 128 + (((q * 2 + aseg) ^ swz) << 4));
            ldsm4(a0, aa);
            ldsm4(a1, aa + 16 * 128);
            uint32_t breg[4][4];
            const uint32_t ba = Bb + (uint32_t)(brow * 128 + (((q * 2 + bseg) ^ swz) << 4));
#pragma unroll
            for (int u = 0; u < 4; u++) ldsm4(breg[u], ba + (uint32_t)(u * 16 * 128));
#pragma unroll
            for (int mf = 0; mf < 2; mf++) {
                uint32_t* A = mf ? a1 : a0;
#pragma unroll
                for (int nf = 0; nf < 8; nf++)
                    mma16816(acc[mf][nf], A, breg[nf >> 1] + (nf & 1) * 2);
            }
        }

        if ((t & 15) == 15) {
            const int nc = t >> 4;
#pragma unroll
            for (int mf = 0; mf < 2; mf++)
#pragma unroll
                for (int nf = 0; nf < 8; nf++) {
                    const int h0 = nc * BN + wn * 64 + nf * 8 + (lane & 3) * 2;
                    const float q0 = s_qw[h0], q1 = s_qw[h0 + 1];
                    const float v0 = s_va[h0], v1 = s_va[h0 + 1];
                    float* c = acc[mf][nf];
                    rowacc[mf * 2 + 0] += fast_tanh(c[0] + q0) * v0 + fast_tanh(c[1] + q1) * v1;
                    rowacc[mf * 2 + 1] += fast_tanh(c[2] + q0) * v0 + fast_tanh(c[3] + q1) * v1;
                    c[0] = 0.f; c[1] = 0.f; c[2] = 0.f; c[3] = 0.f;
                }
        }
    }

    // reduce over the 4 col-lanes of each quad
#pragma unroll
    for (int d = 1; d < 4; d <<= 1)
#pragma unroll
        for (int i = 0; i < 4; i++)
            rowacc[i] += __shfl_xor_sync(0xffffffffu, rowacc[i], d);

    if ((lane & 3) == 0) {
        const int r0 = wm * 32 + (lane >> 2);
        s_red[(r0 +  0) * 2 + wn] = rowacc[0];
        s_red[(r0 +  8) * 2 + wn] = rowacc[1];
        s_red[(r0 + 16) * 2 + wn] = rowacc[2];
        s_red[(r0 + 24) * 2 + wn] = rowacc[3];
    }
    __syncthreads();
    if (tid < 128)
        g_scores[b * SS + s0 + tid] = s_red[tid * 2] + s_red[tid * 2 + 1];
}

// ---------------------------------------------------------------------------
// softmax over S per batch (va_b softmax-invariant, dropped)
// ---------------------------------------------------------------------------
__global__ void softmax_kernel(float* __restrict__ out) {
    const int b = blockIdx.x, tid = threadIdx.x;
    __shared__ float red[256];
    float local[8];
    float mx = -1e30f;
#pragma unroll
    for (int j = 0; j < 8; j++) {
        local[j] = g_scores[b * SS + tid + j * 256];
        mx = fmaxf(mx, local[j]);
    }
    red[tid] = mx; __syncthreads();
    for (int off = 128; off > 0; off >>= 1) {
        if (tid < off) red[tid] = fmaxf(red[tid], red[tid + off]);
        __syncthreads();
    }
    const float m = red[0]; __syncthreads();
    float sum = 0.f;
#pragma unroll
    for (int j = 0; j < 8; j++) { local[j] = expf(local[j] - m); sum += local[j]; }
    red[tid] = sum; __syncthreads();
    for (int off = 128; off > 0; off >>= 1) {
        if (tid < off) red[tid] += red[tid + off];
        __syncthreads();
    }
    const float inv = 1.0f / red[0];
#pragma unroll
    for (int j = 0; j < 8; j++) {
        const float w = local[j] * inv;
        const int s = tid + j * 256;
        out[BB * HH + b * SS + s] = w;
        g_scores[b * SS + s] = w;
    }
}

// ---------------------------------------------------------------------------
// context: partials over 16 s-chunks from fp16 key (half the bytes), then reduce
// ---------------------------------------------------------------------------
__global__ void context_part_kernel() {
    const int b = blockIdx.x, sp = blockIdx.y, tid = threadIdx.x;
    const int s0 = sp * 128;
    __shared__ float ws[128];
    if (tid < 128) ws[tid] = g_scores[b * SS + s0 + tid];
    __syncthreads();
    float4 acc = make_float4(0.f, 0.f, 0.f, 0.f);
    // each thread: 4 consecutive h (two __half2), 256 threads cover H=1024
    const __half2* kp = (const __half2*)(g_k16 + ((size_t)s0 * BB + b) * HH) + tid * 2;
#pragma unroll 4
    for (int s = 0; s < 128; s++) {
        const float w = ws[s];
        const __half2 v01 = kp[(size_t)s * BB * (HH / 2)];
        const __half2 v23 = kp[(size_t)s * BB * (HH / 2) + 1];
        const float2 f01 = __half22float2(v01);
        const float2 f23 = __half22float2(v23);
        acc.x += w * f01.x; acc.y += w * f01.y; acc.z += w * f23.x; acc.w += w * f23.y;
    }
    ((float4*)g_ctx_part)[((size_t)sp * BB + b) * 256 + tid] = acc;
}

__global__ void ctx_reduce_kernel(float* __restrict__ out) {
    const int t = blockIdx.x * 256 + threadIdx.x;  // 8192 float4 outputs
    float4 acc = make_float4(0.f, 0.f, 0.f, 0.f);
#pragma unroll
    for (int sp = 0; sp < 16; sp++) {
        const float4 v = ((const float4*)g_ctx_part)[(size_t)sp * 8192 + t];
        acc.x += v.x; acc.y += v.y; acc.z += v.z; acc.w += v.w;
    }
    ((float4*)out)[t] = acc;
}

// ---------------------------------------------------------------------------
extern "C" void kernel_launch(void* const* d_in, const int* in_sizes, int n_in,
                              void* d_out, int out_size) {
    (void)in_sizes; (void)n_in; (void)out_size;
    const float* query = (const float*)d_in[0];
    const float* key   = (const float*)d_in[1];
    const float* Wa_w  = (const float*)d_in[2];
    const float* Wa_b  = (const float*)d_in[3];
    const float* Ua_w  = (const float*)d_in[4];
    const float* Ua_b  = (const float*)d_in[5];
    const float* va_w  = (const float*)d_in[6];
    float* out = (float*)d_out;  // [context (B*H) | weights (B*S)]

    cudaFuncSetAttribute(scores_kernel, cudaFuncAttributeMaxDynamicSharedMemorySize, SM_TOT);

    convert_key_kernel<<<65536, 256>>>((const float4*)key);
    convert_ua_kernel<<<dim3(HH / 32, HH / 32), dim3(32, 8)>>>(Ua_w);
    qw_kernel<<<dim3(HH / 256, BB / 4), 256>>>(query, Wa_w, Wa_b, Ua_b);
    scores_kernel<<<dim3(SS / BM, BB), 256, SM_TOT>>>(va_w);
    softmax_kernel<<<BB, 256>>>(out);
    context_part_kernel<<<dim3(BB, 16), 256>>>();
    ctx_reduce_kernel<<<32, 256>>>(out);
}

// round 9
// speedup vs baseline: 9.2439x; 1.2796x over previous
#include <cuda_runtime.h>
#include <cuda_fp16.h>
#include <math.h>
#include <stdint.h>

#define BB 32
#define SS 2048
#define HH 1024

// ---------------- device scratch ----------------
__device__ float  g_qw[BB * HH];
__device__ float  g_scores[BB * SS];
__device__ float  g_spart[4 * BB * SS];          // split-H score partials
__device__ __half g_k16[(size_t)SS * BB * HH];   // key fp16, same (S,B,H) layout
__device__ __half g_uT16[(size_t)HH * HH];       // Ua^T fp16, [n][k]
__device__ float  g_ctx_part[16 * BB * HH];

// ---------------- helpers (base-ISA only) ----------------
__device__ __forceinline__ uint32_t smem_u32(const void* p) {
    uint32_t a;
    asm("{ .reg .u64 t; cvta.to.shared.u64 t, %1; cvt.u32.u64 %0, t; }" : "=r"(a) : "l"(p));
    return a;
}
__device__ __forceinline__ void cp16(uint32_t dst, const void* src) {
    asm volatile("cp.async.cg.shared.global [%0], [%1], 16;" :: "r"(dst), "l"(src));
}
__device__ __forceinline__ void cp_commit() { asm volatile("cp.async.commit_group;"); }
__device__ __forceinline__ void ldsm4(uint32_t* r, uint32_t a) {
    asm volatile("ldmatrix.sync.aligned.m8n8.x4.shared.b16 {%0,%1,%2,%3}, [%4];"
                 : "=r"(r[0]), "=r"(r[1]), "=r"(r[2]), "=r"(r[3]) : "r"(a));
}
__device__ __forceinline__ void mma16816(float* c, const uint32_t* a, const uint32_t* b) {
    asm volatile(
        "mma.sync.aligned.m16n8k16.row.col.f32.f16.f16.f32 "
        "{%0,%1,%2,%3}, {%4,%5,%6,%7}, {%8,%9}, {%0,%1,%2,%3};"
        : "+f"(c[0]), "+f"(c[1]), "+f"(c[2]), "+f"(c[3])
        : "r"(a[0]), "r"(a[1]), "r"(a[2]), "r"(a[3]), "r"(b[0]), "r"(b[1]));
}
__device__ __forceinline__ float fast_tanh(float x) {
    float y; asm("tanh.approx.f32 %0, %1;" : "=f"(y) : "f"(x)); return y;
}

// ---------------------------------------------------------------------------
// key fp32 -> fp16 (same (S,B,H) layout)
// ---------------------------------------------------------------------------
__global__ void convert_key_kernel(const float4* __restrict__ k4) {
    const size_t i = (size_t)blockIdx.x * 256 + threadIdx.x;  // 16.7M float4
    const float4 v = k4[i];
    __half2* dst = (__half2*)g_k16;
    dst[i * 2 + 0] = __floats2half2_rn(v.x, v.y);
    dst[i * 2 + 1] = __floats2half2_rn(v.z, v.w);
}

// ---------------------------------------------------------------------------
// Ua (H,H) -> Ua^T fp16 [n][k]
// ---------------------------------------------------------------------------
__global__ void convert_ua_kernel(const float* __restrict__ Ua) {
    __shared__ float tile[32][33];
    const int k0 = blockIdx.x * 32, n0 = blockIdx.y * 32;
    const int tx = threadIdx.x, ty = threadIdx.y;  // (32, 8)
#pragma unroll
    for (int r = 0; r < 4; r++)
        tile[ty + r * 8][tx] = Ua[(size_t)(k0 + ty + r * 8) * HH + n0 + tx];
    __syncthreads();
#pragma unroll
    for (int r = 0; r < 4; r++)
        g_uT16[(size_t)(n0 + ty + r * 8) * HH + k0 + tx] = __float2half(tile[tx][ty + r * 8]);
}

// ---------------------------------------------------------------------------
// qw[b][h] = q[b] @ Wa + Wa_b + Ua_b.  grid (HH/128, BB), 128 threads.
// ---------------------------------------------------------------------------
__global__ void qw_kernel(const float* __restrict__ q, const float* __restrict__ Wa,
                          const float* __restrict__ Wab, const float* __restrict__ Uab) {
    const int b = blockIdx.y;
    const int h = blockIdx.x * 128 + threadIdx.x;
    __shared__ float qs[HH];
    for (int i = threadIdx.x; i < HH; i += 128) qs[i] = q[b * HH + i];
    __syncthreads();
    float a0 = 0.f, a1 = 0.f, a2 = 0.f, a3 = 0.f;
#pragma unroll 4
    for (int k = 0; k < HH; k += 4) {
        a0 += qs[k + 0] * Wa[(size_t)(k + 0) * HH + h];
        a1 += qs[k + 1] * Wa[(size_t)(k + 1) * HH + h];
        a2 += qs[k + 2] * Wa[(size_t)(k + 2) * HH + h];
        a3 += qs[k + 3] * Wa[(size_t)(k + 3) * HH + h];
    }
    g_qw[b * HH + h] = (a0 + a1) + (a2 + a3) + Wab[h] + Uab[h];
}

// ---------------------------------------------------------------------------
// scores via mma.sync fp16, SPLIT-H: grid (16, 32, 4). CTA z handles n-chunks
// {2z, 2z+1} = h range [z*256, z*256+256), writes partial score to g_spart[z].
// BM=128, BN=128, BK=64; 8 warps (4m x 2n); 3-stage cp.async pipeline.
// ---------------------------------------------------------------------------
#define BM 128
#define BN 128
#define BK 64
#define NTL 32                     // tiles per CTA: 2 chunks x 16 k-tiles

#define SM_QW   0u                 // 1 KB used (256 floats)
#define SM_VA   4096u              // 1 KB used
#define SM_RED  8192u              // 1 KB
#define SM_TILE 12288u
#define STAGE_B 32768u
#define SM_TOT  (SM_TILE + 3u * STAGE_B)   // 110592 B

__global__ void __launch_bounds__(256, 2)
scores_kernel(const float* __restrict__ va) {
    extern __shared__ char sm[];
    const int tid = threadIdx.x, lane = tid & 31, wid = tid >> 5;
    const int wm = wid & 3, wn = wid >> 2;     // warp grid 4(m) x 2(n)
    const int b = blockIdx.y, s0 = blockIdx.x * BM, z = blockIdx.z;
    const uint32_t sb = smem_u32(sm);
    float* s_qw  = (float*)(sm + SM_QW);
    float* s_va  = (float*)(sm + SM_VA);
    float* s_red = (float*)(sm + SM_RED);

    // this CTA's 256-entry h-slice: [z*256, z*256+256)  (2 chunks x BN=128)
    s_qw[tid] = g_qw[b * HH + z * 256 + tid];
    s_va[tid] = va[z * 256 + tid];

    // cp.async per-thread assignments: 128 rows x 8 segs(16B), XOR swizzle.
    uint32_t a_dst[4];
    const __half* a_src[4];
    uint32_t b_off[4];
#pragma unroll
    for (int i = 0; i < 4; i++) {
        const int c = tid + i * 256, row = c >> 3, seg = c & 7;
        a_dst[i] = (uint32_t)(row * 128 + ((seg ^ (row & 7)) << 4));
        a_src[i] = g_k16 + ((size_t)(s0 + row) * BB + b) * HH + seg * 8;
        b_off[i] = (uint32_t)(row * HH + seg * 8);
    }

    // ldmatrix per-lane components
    const int arow = wm * 32 + (lane & 15);
    const int aseg = lane >> 4;
    const int brow = wn * 64 + (lane & 7) + ((lane & 16) >> 1);
    const int bseg = (lane >> 3) & 1;
    const int swz  = lane & 7;

    float rowacc[4] = {0.f, 0.f, 0.f, 0.f};
    float acc[2][8][4];
#pragma unroll
    for (int mf = 0; mf < 2; mf++)
#pragma unroll
        for (int nf = 0; nf < 8; nf++)
#pragma unroll
            for (int j = 0; j < 4; j++) acc[mf][nf][j] = 0.f;

    // tile issuer: tile t (0..31) -> stage t%3; nc = 2z + (t>>4)
    auto issue = [&](int t) {
        const int nc = 2 * z + (t >> 4), k0 = (t & 15) * BK;
        const uint32_t st = sb + SM_TILE + (uint32_t)(t % 3) * STAGE_B;
        const __half* uTp = g_uT16 + (size_t)(nc * BN) * HH + k0;
#pragma unroll
        for (int i = 0; i < 4; i++) cp16(st + a_dst[i], a_src[i] + k0);
#pragma unroll
        for (int i = 0; i < 4; i++) cp16(st + 16384u + a_dst[i], uTp + b_off[i]);
        cp_commit();
    };

    issue(0);
    issue(1);

    for (int t = 0; t < NTL; t++) {
        if (t + 1 < NTL) asm volatile("cp.async.wait_group 1;");
        else             asm volatile("cp.async.wait_group 0;");
        __syncthreads();
        if (t + 2 < NTL) issue(t + 2);

        const uint32_t Ab = sb + SM_TILE + (uint32_t)(t % 3) * STAGE_B;
        const uint32_t Bb = Ab + 16384u;

#pragma unroll
        for (int q = 0; q < 4; q++) {
            uint32_t a0[4], a1[4];
            const uint32_t aa = Ab + (uint32_t)(arow * 128 + (((q * 2 + aseg) ^ swz) << 4));
            ldsm4(a0, aa);
            ldsm4(a1, aa + 16 * 128);
            uint32_t breg[4][4];
            const uint32_t ba = Bb + (uint32_t)(brow * 128 + (((q * 2 + bseg) ^ swz) << 4));
#pragma unroll
            for (int u = 0; u < 4; u++) ldsm4(breg[u], ba + (uint32_t)(u * 16 * 128));
#pragma unroll
            for (int mf = 0; mf < 2; mf++) {
                uint32_t* A = mf ? a1 : a0;
#pragma unroll
                for (int nf = 0; nf < 8; nf++)
                    mma16816(acc[mf][nf], A, breg[nf >> 1] + (nf & 1) * 2);
            }
        }

        if ((t & 15) == 15) {
            const int cl = t >> 4;   // local chunk 0/1 -> local h base 0/128
#pragma unroll
            for (int mf = 0; mf < 2; mf++)
#pragma unroll
                for (int nf = 0; nf < 8; nf++) {
                    const int h0 = cl * BN + wn * 64 + nf * 8 + (lane & 3) * 2;  // [0,256)
                    const float q0 = s_qw[h0], q1 = s_qw[h0 + 1];
                    const float v0 = s_va[h0], v1 = s_va[h0 + 1];
                    float* c = acc[mf][nf];
                    rowacc[mf * 2 + 0] += fast_tanh(c[0] + q0) * v0 + fast_tanh(c[1] + q1) * v1;
                    rowacc[mf * 2 + 1] += fast_tanh(c[2] + q0) * v0 + fast_tanh(c[3] + q1) * v1;
                    c[0] = 0.f; c[1] = 0.f; c[2] = 0.f; c[3] = 0.f;
                }
        }
    }

    // reduce over the 4 col-lanes of each quad
#pragma unroll
    for (int d = 1; d < 4; d <<= 1)
#pragma unroll
        for (int i = 0; i < 4; i++)
            rowacc[i] += __shfl_xor_sync(0xffffffffu, rowacc[i], d);

    if ((lane & 3) == 0) {
        const int r0 = wm * 32 + (lane >> 2);
        s_red[(r0 +  0) * 2 + wn] = rowacc[0];
        s_red[(r0 +  8) * 2 + wn] = rowacc[1];
        s_red[(r0 + 16) * 2 + wn] = rowacc[2];
        s_red[(r0 + 24) * 2 + wn] = rowacc[3];
    }
    __syncthreads();
    if (tid < 128)
        g_spart[(z * BB + b) * SS + s0 + tid] = s_red[tid * 2] + s_red[tid * 2 + 1];
}

// ---------------------------------------------------------------------------
// softmax over S per batch; sums the 4 split-H partials first.
// ---------------------------------------------------------------------------
__global__ void softmax_kernel(float* __restrict__ out) {
    const int b = blockIdx.x, tid = threadIdx.x;
    __shared__ float red[256];
    float local[8];
    float mx = -1e30f;
#pragma unroll
    for (int j = 0; j < 8; j++) {
        const int s = tid + j * 256;
        local[j] = (g_spart[(0 * BB + b) * SS + s] + g_spart[(1 * BB + b) * SS + s])
                 + (g_spart[(2 * BB + b) * SS + s] + g_spart[(3 * BB + b) * SS + s]);
        mx = fmaxf(mx, local[j]);
    }
    red[tid] = mx; __syncthreads();
    for (int off = 128; off > 0; off >>= 1) {
        if (tid < off) red[tid] = fmaxf(red[tid], red[tid + off]);
        __syncthreads();
    }
    const float m = red[0]; __syncthreads();
    float sum = 0.f;
#pragma unroll
    for (int j = 0; j < 8; j++) { local[j] = expf(local[j] - m); sum += local[j]; }
    red[tid] = sum; __syncthreads();
    for (int off = 128; off > 0; off >>= 1) {
        if (tid < off) red[tid] += red[tid + off];
        __syncthreads();
    }
    const float inv = 1.0f / red[0];
#pragma unroll
    for (int j = 0; j < 8; j++) {
        const float w = local[j] * inv;
        const int s = tid + j * 256;
        out[BB * HH + b * SS + s] = w;
        g_scores[b * SS + s] = w;
    }
}

// ---------------------------------------------------------------------------
// context: partials over 16 s-chunks from fp16 key, then reduce
// ---------------------------------------------------------------------------
__global__ void context_part_kernel() {
    const int b = blockIdx.x, sp = blockIdx.y, tid = threadIdx.x;
    const int s0 = sp * 128;
    __shared__ float ws[128];
    if (tid < 128) ws[tid] = g_scores[b * SS + s0 + tid];
    __syncthreads();
    float4 acc = make_float4(0.f, 0.f, 0.f, 0.f);
    const __half2* kp = (const __half2*)(g_k16 + ((size_t)s0 * BB + b) * HH) + tid * 2;
#pragma unroll 4
    for (int s = 0; s < 128; s++) {
        const float w = ws[s];
        const __half2 v01 = kp[(size_t)s * BB * (HH / 2)];
        const __half2 v23 = kp[(size_t)s * BB * (HH / 2) + 1];
        const float2 f01 = __half22float2(v01);
        const float2 f23 = __half22float2(v23);
        acc.x += w * f01.x; acc.y += w * f01.y; acc.z += w * f23.x; acc.w += w * f23.y;
    }
    ((float4*)g_ctx_part)[((size_t)sp * BB + b) * 256 + tid] = acc;
}

__global__ void ctx_reduce_kernel(float* __restrict__ out) {
    const int t = blockIdx.x * 256 + threadIdx.x;  // 8192 float4 outputs
    float4 acc = make_float4(0.f, 0.f, 0.f, 0.f);
#pragma unroll
    for (int sp = 0; sp < 16; sp++) {
        const float4 v = ((const float4*)g_ctx_part)[(size_t)sp * 8192 + t];
        acc.x += v.x; acc.y += v.y; acc.z += v.z; acc.w += v.w;
    }
    ((float4*)out)[t] = acc;
}

// ---------------------------------------------------------------------------
extern "C" void kernel_launch(void* const* d_in, const int* in_sizes, int n_in,
                              void* d_out, int out_size) {
    (void)in_sizes; (void)n_in; (void)out_size;
    const float* query = (const float*)d_in[0];
    const float* key   = (const float*)d_in[1];
    const float* Wa_w  = (const float*)d_in[2];
    const float* Wa_b  = (const float*)d_in[3];
    const float* Ua_w  = (const float*)d_in[4];
    const float* Ua_b  = (const float*)d_in[5];
    const float* va_w  = (const float*)d_in[6];
    float* out = (float*)d_out;  // [context (B*H) | weights (B*S)]

    cudaFuncSetAttribute(scores_kernel, cudaFuncAttributeMaxDynamicSharedMemorySize, SM_TOT);

    convert_key_kernel<<<65536, 256>>>((const float4*)key);
    convert_ua_kernel<<<dim3(HH / 32, HH / 32), dim3(32, 8)>>>(Ua_w);
    qw_kernel<<<dim3(HH / 128, BB), 128>>>(query, Wa_w, Wa_b, Ua_b);
    scores_kernel<<<dim3(SS / BM, BB, 4), 256, SM_TOT>>>(va_w);
    softmax_kernel<<<BB, 256>>>(out);
    context_part_kernel<<<dim3(BB, 16), 256>>>();
    ctx_reduce_kernel<<<32, 256>>>(out);
}